// round 2
// baseline (speedup 1.0000x reference)
#include <cuda_runtime.h>

#define B_ 4
#define T_ 2048
#define C_ 1024
#define H_ 16
#define HD_ 64
#define QKVC (3 * C_)

// Scratch (no cudaMalloc allowed): qkv = 96 MB, y = 32 MB
__device__ float g_qkv[(size_t)B_ * T_ * QKVC];
__device__ float g_y[(size_t)B_ * T_ * C_];

// ---------------------------------------------------------------------------
// SGEMM: C[M,N] = A[M,K] @ B[K,N] + bias[N], all row-major.
// 128x128 tile, BK=16, 256 threads, 8x8 micro-tile with split {0,+64}
// rows/cols so smem reads are broadcast (A) or contiguous LDS.128 (B).
// M,N,K are multiples of 128/128/16 for all call sites -> no bounds checks.
// ---------------------------------------------------------------------------
__global__ __launch_bounds__(256) void sgemm_bias_k(
    const float* __restrict__ A, const float* __restrict__ Bm,
    const float* __restrict__ bias, float* __restrict__ C,
    int M, int N, int K)
{
    __shared__ float As[16][128];
    __shared__ float Bs[16][128];
    const int tid = threadIdx.x;
    const int tx = tid & 15, ty = tid >> 4;
    const int bm = blockIdx.y * 128, bn = blockIdx.x * 128;

    float acc[8][8];
#pragma unroll
    for (int i = 0; i < 8; i++)
#pragma unroll
        for (int j = 0; j < 8; j++) acc[i][j] = 0.f;

    for (int k0 = 0; k0 < K; k0 += 16) {
        // A tile: 128 rows x 16 cols, transposed into As[k][m]
#pragma unroll
        for (int i = 0; i < 2; i++) {
            int idx = tid * 2 + i;
            int r = idx >> 2, cv = (idx & 3) << 2;
            float4 v = *(const float4*)(A + (size_t)(bm + r) * K + k0 + cv);
            As[cv + 0][r] = v.x;
            As[cv + 1][r] = v.y;
            As[cv + 2][r] = v.z;
            As[cv + 3][r] = v.w;
        }
        // B tile: 16 rows x 128 cols, direct
#pragma unroll
        for (int i = 0; i < 2; i++) {
            int idx = tid * 2 + i;
            int r = idx >> 5, cv = (idx & 31) << 2;
            *(float4*)(&Bs[r][cv]) =
                *(const float4*)(Bm + (size_t)(k0 + r) * N + bn + cv);
        }
        __syncthreads();
#pragma unroll
        for (int kk = 0; kk < 16; kk++) {
            float a[8], b[8];
            *(float4*)(a)     = *(const float4*)(&As[kk][ty * 4]);
            *(float4*)(a + 4) = *(const float4*)(&As[kk][64 + ty * 4]);
            *(float4*)(b)     = *(const float4*)(&Bs[kk][tx * 4]);
            *(float4*)(b + 4) = *(const float4*)(&Bs[kk][64 + tx * 4]);
#pragma unroll
            for (int i = 0; i < 8; i++)
#pragma unroll
                for (int j = 0; j < 8; j++)
                    acc[i][j] = fmaf(a[i], b[j], acc[i][j]);
        }
        __syncthreads();
    }

#pragma unroll
    for (int i = 0; i < 8; i++) {
        int r = bm + ((i < 4) ? (ty * 4 + i) : (64 + ty * 4 + (i - 4)));
#pragma unroll
        for (int jh = 0; jh < 2; jh++) {
            int c = bn + ((jh == 0) ? (tx * 4) : (64 + tx * 4));
            float4 o;
            o.x = acc[i][jh * 4 + 0] + bias[c + 0];
            o.y = acc[i][jh * 4 + 1] + bias[c + 1];
            o.z = acc[i][jh * 4 + 2] + bias[c + 2];
            o.w = acc[i][jh * 4 + 3] + bias[c + 3];
            *(float4*)(C + (size_t)r * N + c) = o;
        }
    }
}

// ---------------------------------------------------------------------------
// Flash-style attention. Grid (T/64, H, B), 256 threads.
// Per CTA: 64 queries x head-dim 64. Streams 64-key K/V tiles, online
// softmax, P staged in smem for the PV product.
// Thread (tx,ty) in 16x16 layout owns a 4x4 S tile and a 4x4 O tile.
// smem: Qs[64][65] Ks[64][65] Ps[64][65] Vs[64][64] = 66304 B (dynamic).
// ---------------------------------------------------------------------------
__global__ __launch_bounds__(256) void attn_k(const float* __restrict__ qkv,
                                              float* __restrict__ y)
{
    extern __shared__ float sm[];
    float* Qs = sm;               // 64*65
    float* Ks = Qs + 64 * 65;     // 64*65
    float* Ps = Ks + 64 * 65;     // 64*65
    float* Vs = Ps + 64 * 65;     // 64*64

    const int tid = threadIdx.x;
    const int tx = tid & 15, ty = tid >> 4;
    const int q0 = blockIdx.x * 64;
    const int h = blockIdx.y;
    const int b = blockIdx.z;
    const size_t base = (size_t)b * T_ * QKVC;
    const int qoff = h * HD_;
    const int koff = C_ + h * HD_;
    const int voff = 2 * C_ + h * HD_;

    // Load Q tile, pre-scaled by 1/sqrt(D) = 0.125
    for (int i = tid; i < 64 * 16; i += 256) {
        int r = i >> 4, cv = (i & 15) << 2;
        float4 v = *(const float4*)(qkv + base + (size_t)(q0 + r) * QKVC + qoff + cv);
        Qs[r * 65 + cv + 0] = v.x * 0.125f;
        Qs[r * 65 + cv + 1] = v.y * 0.125f;
        Qs[r * 65 + cv + 2] = v.z * 0.125f;
        Qs[r * 65 + cv + 3] = v.w * 0.125f;
    }

    float m_run[4], l_run[4], o[4][4];
#pragma unroll
    for (int i = 0; i < 4; i++) {
        m_run[i] = -1e30f;
        l_run[i] = 0.f;
#pragma unroll
        for (int j = 0; j < 4; j++) o[i][j] = 0.f;
    }

    for (int t0 = 0; t0 < T_; t0 += 64) {
        __syncthreads();  // prev iteration's P*V reads done before K/V overwrite
        for (int i = tid; i < 64 * 16; i += 256) {
            int r = i >> 4, cv = (i & 15) << 2;
            const float* rowp = qkv + base + (size_t)(t0 + r) * QKVC;
            float4 kv = *(const float4*)(rowp + koff + cv);
            Ks[r * 65 + cv + 0] = kv.x;
            Ks[r * 65 + cv + 1] = kv.y;
            Ks[r * 65 + cv + 2] = kv.z;
            Ks[r * 65 + cv + 3] = kv.w;
            *(float4*)(Vs + r * 64 + cv) = *(const float4*)(rowp + voff + cv);
        }
        __syncthreads();

        // S = Q K^T (scale already folded into Q)
        float s[4][4];
#pragma unroll
        for (int i = 0; i < 4; i++)
#pragma unroll
            for (int j = 0; j < 4; j++) s[i][j] = 0.f;

#pragma unroll 16
        for (int kk = 0; kk < 64; kk++) {
            float a[4], bb[4];
#pragma unroll
            for (int i = 0; i < 4; i++) a[i] = Qs[(ty * 4 + i) * 65 + kk];
#pragma unroll
            for (int j = 0; j < 4; j++) bb[j] = Ks[(tx * 4 + j) * 65 + kk];
#pragma unroll
            for (int i = 0; i < 4; i++)
#pragma unroll
                for (int j = 0; j < 4; j++)
                    s[i][j] = fmaf(a[i], bb[j], s[i][j]);
        }

        // row max across the 16-lane tx group (lane = (ty&1)*16 + tx,
        // so xor offsets 1..8 stay within the tx group)
        float mt[4];
#pragma unroll
        for (int i = 0; i < 4; i++)
            mt[i] = fmaxf(fmaxf(s[i][0], s[i][1]), fmaxf(s[i][2], s[i][3]));
#pragma unroll
        for (int off = 8; off > 0; off >>= 1)
#pragma unroll
            for (int i = 0; i < 4; i++)
                mt[i] = fmaxf(mt[i], __shfl_xor_sync(0xffffffffu, mt[i], off));

        float alpha[4], lt[4];
#pragma unroll
        for (int i = 0; i < 4; i++) {
            float mn = fmaxf(m_run[i], mt[i]);
            alpha[i] = __expf(m_run[i] - mn);
            m_run[i] = mn;
            lt[i] = 0.f;
#pragma unroll
            for (int j = 0; j < 4; j++) {
                float p = __expf(s[i][j] - mn);
                s[i][j] = p;
                lt[i] += p;
            }
        }
#pragma unroll
        for (int off = 8; off > 0; off >>= 1)
#pragma unroll
            for (int i = 0; i < 4; i++)
                lt[i] += __shfl_xor_sync(0xffffffffu, lt[i], off);
#pragma unroll
        for (int i = 0; i < 4; i++) l_run[i] = l_run[i] * alpha[i] + lt[i];

        // stage P, rescale O
#pragma unroll
        for (int i = 0; i < 4; i++)
#pragma unroll
            for (int j = 0; j < 4; j++) {
                Ps[(ty * 4 + i) * 65 + tx * 4 + j] = s[i][j];
                o[i][j] *= alpha[i];
            }
        __syncthreads();

        // O += P V
#pragma unroll 16
        for (int kk = 0; kk < 64; kk++) {
            float4 bv = *(const float4*)(Vs + kk * 64 + tx * 4);
#pragma unroll
            for (int i = 0; i < 4; i++) {
                float a = Ps[(ty * 4 + i) * 65 + kk];
                o[i][0] = fmaf(a, bv.x, o[i][0]);
                o[i][1] = fmaf(a, bv.y, o[i][1]);
                o[i][2] = fmaf(a, bv.z, o[i][2]);
                o[i][3] = fmaf(a, bv.w, o[i][3]);
            }
        }
    }

    // normalize + write y[b, q, h*64 + d]
#pragma unroll
    for (int i = 0; i < 4; i++) {
        float inv = 1.f / l_run[i];
        float4 ov;
        ov.x = o[i][0] * inv;
        ov.y = o[i][1] * inv;
        ov.z = o[i][2] * inv;
        ov.w = o[i][3] * inv;
        *(float4*)(y + (size_t)(b * T_ + q0 + ty * 4 + i) * C_ + h * HD_ + tx * 4) = ov;
    }
}

static const int ATTN_SMEM = (3 * 64 * 65 + 64 * 64) * (int)sizeof(float);  // 66304

extern "C" void kernel_launch(void* const* d_in, const int* in_sizes, int n_in,
                              void* d_out, int out_size)
{
    (void)in_sizes; (void)n_in; (void)out_size;
    const float* x      = (const float*)d_in[0];
    const float* W_attn = (const float*)d_in[1];
    const float* b_attn = (const float*)d_in[2];
    const float* W_proj = (const float*)d_in[3];
    const float* b_proj = (const float*)d_in[4];
    float* out = (float*)d_out;

    float* qkv = nullptr;
    float* yb  = nullptr;
    cudaGetSymbolAddress((void**)&qkv, g_qkv);
    cudaGetSymbolAddress((void**)&yb, g_y);

    cudaFuncSetAttribute(attn_k, cudaFuncAttributeMaxDynamicSharedMemorySize,
                         ATTN_SMEM);

    // 1) qkv = x @ W_attn + b_attn       [8192, 3072]
    dim3 g1(QKVC / 128, (B_ * T_) / 128);
    sgemm_bias_k<<<g1, 256>>>(x, W_attn, b_attn, qkv, B_ * T_, QKVC, C_);

    // 2) y = SDPA(q, k, v)               [8192, 1024]
    dim3 ga(T_ / 64, H_, B_);
    attn_k<<<ga, 256, ATTN_SMEM>>>(qkv, yb);

    // 3) out = y @ W_proj + b_proj       [8192, 1024]
    dim3 g2(C_ / 128, (B_ * T_) / 128);
    sgemm_bias_k<<<g2, 256>>>(yb, W_proj, b_proj, out, B_ * T_, C_, C_);
}